// round 4
// baseline (speedup 1.0000x reference)
#include <cuda_runtime.h>
#include <cuda_bf16.h>
#include <cstdint>

// Based linear attention == causal attention with phi(s)=s+0.5*s^2, s=scale*(q.k).
// Warp-level mma.sync (bf16 m16n8k16) flash kernel, fp32 accuracy via split-bf16
// (x = hi + lo; 3 passes hi*hi + hi*lo + lo*hi, fp32 accumulation).
// R4: cp.async software pipeline — raw fp32 K/V tiles staged into smem one
// iteration ahead; conversion reads smem, GEMM phase hides global latency.

#define BB 2
#define HH 16
#define SEQ 2048
#define DD 64
#define QROWS 128
#define KROWS 64
#define NQT (SEQ / QROWS)   // 16
#define NBH (BB * HH)       // 32

// dynamic smem layout (bytes)
#define OFF_KHI  0
#define OFF_KLO  8192
#define OFF_VHI  16384
#define OFF_VLO  24576
#define OFF_KRAW 32768
#define OFF_VRAW 49152
#define SMEM_TOTAL 65536

__device__ __forceinline__ uint32_t smem_u32(const void* p) {
    uint32_t a;
    asm("{ .reg .u64 t; cvta.to.shared.u64 t, %1; cvt.u32.u64 %0, t; }" : "=r"(a) : "l"(p));
    return a;
}

// byte-offset swizzle for 128B rows: XOR row[2:0] into 16B-chunk index
__device__ __forceinline__ uint32_t swz(uint32_t b) { return b ^ ((b >> 3) & 0x70); }

__device__ __forceinline__ void mma_bf16(float* c, uint32_t a0, uint32_t a1,
                                         uint32_t a2, uint32_t a3,
                                         uint32_t b0, uint32_t b1) {
    asm volatile(
        "mma.sync.aligned.m16n8k16.row.col.f32.bf16.bf16.f32 "
        "{%0,%1,%2,%3}, {%4,%5,%6,%7}, {%8,%9}, {%0,%1,%2,%3};"
        : "+f"(c[0]), "+f"(c[1]), "+f"(c[2]), "+f"(c[3])
        : "r"(a0), "r"(a1), "r"(a2), "r"(a3), "r"(b0), "r"(b1));
}

__device__ __forceinline__ void ldsm4(uint32_t* r, uint32_t addr) {
    asm volatile("ldmatrix.sync.aligned.m8n8.x4.shared.b16 {%0,%1,%2,%3}, [%4];"
                 : "=r"(r[0]), "=r"(r[1]), "=r"(r[2]), "=r"(r[3]) : "r"(addr));
}
__device__ __forceinline__ void ldsm4t(uint32_t* r, uint32_t addr) {
    asm volatile("ldmatrix.sync.aligned.m8n8.x4.trans.shared.b16 {%0,%1,%2,%3}, [%4];"
                 : "=r"(r[0]), "=r"(r[1]), "=r"(r[2]), "=r"(r[3]) : "r"(addr));
}

__device__ __forceinline__ void cp_async16(uint32_t smem_dst, const void* gptr) {
    asm volatile("cp.async.cg.shared.global [%0], [%1], 16;"
                 :: "r"(smem_dst), "l"(gptr) : "memory");
}
#define CP_COMMIT() asm volatile("cp.async.commit_group;" ::: "memory")
#define CP_WAIT0()  asm volatile("cp.async.wait_group 0;" ::: "memory")

// split (x,y) into packed bf16x2 hi and lo (residual) words
__device__ __forceinline__ void split2(float x, float y, uint32_t& hi, uint32_t& lo) {
    __nv_bfloat162 h = __floats2bfloat162_rn(x, y);
    float2 hf = __bfloat1622float2(h);
    __nv_bfloat162 l = __floats2bfloat162_rn(x - hf.x, y - hf.y);
    hi = *reinterpret_cast<uint32_t*>(&h);
    lo = *reinterpret_cast<uint32_t*>(&l);
}

__global__ __launch_bounds__(256, 2)
void based_mma_kernel(const float* __restrict__ q, const float* __restrict__ k,
                      const float* __restrict__ v, float* __restrict__ out)
{
    extern __shared__ char sm[];
    const uint32_t sbase = smem_u32(sm);

    const int tid  = threadIdx.x;
    const int lane = tid & 31;
    const int w    = tid >> 5;          // warp 0..7, owns q-rows [16w,16w+16)
    const int g    = lane >> 2;
    const int t4   = lane & 3;

    const int bh = blockIdx.y;
    const int qt = (NQT - 1) - blockIdx.x;   // big q-tiles first
    const size_t head = (size_t)bh * SEQ * DD;
    const int nkt = 2 * qt + 2;

    const float* kg0 = k + head;
    const float* vg0 = v + head;

    // ---- prologue: stage K/V tile 0 (overlaps with Q fragment loading) ----
    {
        #pragma unroll
        for (int it = 0; it < 4; ++it) {
            int idx = tid + it * 256;       // float4 chunks 0..1023
            cp_async16(sbase + OFF_KRAW + idx * 16, kg0 + idx * 4);
            cp_async16(sbase + OFF_VRAW + idx * 16, vg0 + idx * 4);
        }
        CP_COMMIT();
    }

    // ---- Q fragments: register-resident for the whole CTA lifetime ----
    uint32_t qh[4][4], ql[4][4];
    const int r0 = qt * QROWS + w * 16 + g;
    {
        const float scale = 0.125f;
        const float* qb = q + head;
        #pragma unroll
        for (int kb = 0; kb < 4; ++kb)
            #pragma unroll
            for (int h = 0; h < 4; ++h) {
                int row = r0 + ((h & 1) ? 8 : 0);
                int col = kb * 16 + t4 * 2 + ((h & 2) ? 8 : 0);
                float2 val = *reinterpret_cast<const float2*>(qb + (size_t)row * DD + col);
                split2(val.x * scale, val.y * scale, qh[kb][h], ql[kb][h]);
            }
    }

    float oacc[8][4] = {};

    const uint32_t kh_b = sbase + OFF_KHI, kl_b = sbase + OFF_KLO;
    const uint32_t vh_b = sbase + OFF_VHI, vl_b = sbase + OFF_VLO;
    const uint32_t sw = (lane & 7) << 4;
    const int rowK = ((lane >> 3) & 1) * 8 + (lane & 7);
    const int colK = (lane >> 4) * 16;
    const int rowV = ((lane >> 4) & 1) * 8 + (lane & 7);
    const int colV = ((lane >> 3) & 1) * 16;

    const float4* kraw = reinterpret_cast<const float4*>(sm + OFF_KRAW);
    const float4* vraw = reinterpret_cast<const float4*>(sm + OFF_VRAW);

    for (int kt = 0; kt < nkt; ++kt) {
        CP_WAIT0();            // raw tile kt landed (this thread's copies)
        __syncthreads();       // all threads' copies visible; prev GEMM readers done

        // ---- convert raw fp32 (smem) -> bf16 hi/lo tiles (swizzled) ----
        #pragma unroll
        for (int it = 0; it < 4; ++it) {
            int idx = tid + it * 256;
            int r = idx >> 4, c4 = idx & 15;
            uint32_t so = swz((uint32_t)(r * 128 + c4 * 8));

            float4 kv = kraw[idx];
            uint32_t h0, l0, h1, l1;
            split2(kv.x, kv.y, h0, l0);
            split2(kv.z, kv.w, h1, l1);
            *reinterpret_cast<uint2*>(sm + OFF_KHI + so) = make_uint2(h0, h1);
            *reinterpret_cast<uint2*>(sm + OFF_KLO + so) = make_uint2(l0, l1);

            float4 vv = vraw[idx];
            split2(vv.x, vv.y, h0, l0);
            split2(vv.z, vv.w, h1, l1);
            *reinterpret_cast<uint2*>(sm + OFF_VHI + so) = make_uint2(h0, h1);
            *reinterpret_cast<uint2*>(sm + OFF_VLO + so) = make_uint2(l0, l1);
        }
        __syncthreads();       // bf16 ready; raw fully consumed

        // ---- prefetch next raw tile (covered by the GEMM phase below) ----
        if (kt + 1 < nkt) {
            const float* kg = kg0 + (size_t)(kt + 1) * KROWS * DD;
            const float* vg = vg0 + (size_t)(kt + 1) * KROWS * DD;
            #pragma unroll
            for (int it = 0; it < 4; ++it) {
                int idx = tid + it * 256;
                cp_async16(sbase + OFF_KRAW + idx * 16, kg + idx * 4);
                cp_async16(sbase + OFF_VRAW + idx * 16, vg + idx * 4);
            }
            CP_COMMIT();
        }

        // ---- GEMM1: S[16x64] = Q_w * K^T  (3 split passes per B load) ----
        float sacc[8][4] = {};
        #pragma unroll
        for (int kk = 0; kk < 4; ++kk) {
            #pragma unroll
            for (int p = 0; p < 4; ++p) {
                uint32_t off = (uint32_t)((16 * p + rowK) * 128) + (((uint32_t)(32 * kk + colK)) ^ sw);
                uint32_t bhr[4], blr[4];
                ldsm4(bhr, kh_b + off);
                ldsm4(blr, kl_b + off);
                mma_bf16(sacc[2*p],   qh[kk][0],qh[kk][1],qh[kk][2],qh[kk][3], bhr[0], bhr[2]);
                mma_bf16(sacc[2*p+1], qh[kk][0],qh[kk][1],qh[kk][2],qh[kk][3], bhr[1], bhr[3]);
                mma_bf16(sacc[2*p],   qh[kk][0],qh[kk][1],qh[kk][2],qh[kk][3], blr[0], blr[2]);
                mma_bf16(sacc[2*p+1], qh[kk][0],qh[kk][1],qh[kk][2],qh[kk][3], blr[1], blr[3]);
                mma_bf16(sacc[2*p],   ql[kk][0],ql[kk][1],ql[kk][2],ql[kk][3], bhr[0], bhr[2]);
                mma_bf16(sacc[2*p+1], ql[kk][0],ql[kk][1],ql[kk][2],ql[kk][3], bhr[1], bhr[3]);
            }
        }

        // ---- phi(s)=s+0.5s^2, causal mask, split into GEMM2 A-fragments ----
        uint32_t ah[4][4], al[4][4];
        const bool edge = (kt >= 2 * qt);
        #pragma unroll
        for (int nb = 0; nb < 8; ++nb) {
            int colg = kt * KROWS + nb * 8 + 2 * t4;
            float e[4];
            #pragma unroll
            for (int u = 0; u < 4; ++u) {
                float s = sacc[nb][u];
                float p = fmaf(0.5f * s, s, s);
                if (edge && (colg + (u & 1) > r0 + ((u & 2) ? 8 : 0))) p = 0.0f;
                e[u] = p;
            }
            int kk = nb >> 1, half = (nb & 1) * 2;
            split2(e[0], e[1], ah[kk][half],     al[kk][half]);
            split2(e[2], e[3], ah[kk][half + 1], al[kk][half + 1]);
        }

        // ---- GEMM2: O += phi(S) * V  (V via ldmatrix.trans) ----
        #pragma unroll
        for (int kk = 0; kk < 4; ++kk) {
            #pragma unroll
            for (int p = 0; p < 4; ++p) {
                uint32_t off = (uint32_t)((16 * kk + rowV) * 128) + (((uint32_t)(32 * p + colV)) ^ sw);
                uint32_t vhr[4], vlr[4];
                ldsm4t(vhr, vh_b + off);
                ldsm4t(vlr, vl_b + off);
                mma_bf16(oacc[2*p],   ah[kk][0],ah[kk][1],ah[kk][2],ah[kk][3], vhr[0], vhr[2]);
                mma_bf16(oacc[2*p+1], ah[kk][0],ah[kk][1],ah[kk][2],ah[kk][3], vhr[1], vhr[3]);
                mma_bf16(oacc[2*p],   ah[kk][0],ah[kk][1],ah[kk][2],ah[kk][3], vlr[0], vlr[2]);
                mma_bf16(oacc[2*p+1], ah[kk][0],ah[kk][1],ah[kk][2],ah[kk][3], vlr[1], vlr[3]);
                mma_bf16(oacc[2*p],   al[kk][0],al[kk][1],al[kk][2],al[kk][3], vhr[0], vhr[2]);
                mma_bf16(oacc[2*p+1], al[kk][0],al[kk][1],al[kk][2],al[kk][3], vhr[1], vhr[3]);
            }
        }
    }

    // ---- store O fragments ----
    float* og = out + head;
    #pragma unroll
    for (int nb = 0; nb < 8; ++nb) {
        int col = nb * 8 + 2 * t4;
        *reinterpret_cast<float2*>(og + (size_t)r0 * DD + col) =
            make_float2(oacc[nb][0], oacc[nb][1]);
        *reinterpret_cast<float2*>(og + (size_t)(r0 + 8) * DD + col) =
            make_float2(oacc[nb][2], oacc[nb][3]);
    }
}

extern "C" void kernel_launch(void* const* d_in, const int* in_sizes, int n_in,
                              void* d_out, int out_size) {
    const float* q = (const float*)d_in[0];
    const float* k = (const float*)d_in[1];
    const float* v = (const float*)d_in[2];
    float* out = (float*)d_out;

    static bool attr_set = false;
    if (!attr_set) {
        cudaFuncSetAttribute(based_mma_kernel,
                             cudaFuncAttributeMaxDynamicSharedMemorySize, SMEM_TOTAL);
        attr_set = true;
    }
    dim3 grid(NQT, NBH);
    based_mma_kernel<<<grid, 256, SMEM_TOTAL>>>(q, k, v, out);
}

// round 5
// speedup vs baseline: 1.0808x; 1.0808x over previous
#include <cuda_runtime.h>
#include <cuda_bf16.h>
#include <cstdint>

// Based linear attention == causal attention with phi(s)=s+0.5*s^2, s=scale*(q.k).
// Warp-level mma.sync (bf16 m16n8k16), fp32 accuracy via split-bf16 (x = hi+lo;
// 3 passes hi*hi + hi*lo + lo*hi, fp32 accumulation).
// R5: K/V split to bf16 hi/lo ONCE in a prepass into __device__ scratch; the
// main loop cp.async's ready bf16 tiles (double-buffered) — no convert phase.

#define BB 2
#define HH 16
#define SEQ 2048
#define DD 64
#define QROWS 128
#define KROWS 64
#define NQT (SEQ / QROWS)   // 16
#define NBH (BB * HH)       // 32
#define TOTAL_ELEMS (NBH * SEQ * DD)        // 4,194,304
#define TOTAL_F4    (TOTAL_ELEMS / 4)       // 1,048,576

// pre-split bf16 scratch (uint2 = 4 bf16), element order == original fp32 order
__device__ uint2 g_khi[TOTAL_F4];
__device__ uint2 g_klo[TOTAL_F4];
__device__ uint2 g_vhi[TOTAL_F4];
__device__ uint2 g_vlo[TOTAL_F4];

// dynamic smem: 2 stages x (khi,klo,vhi,vlo) 8KB each
#define STAGE_BYTES 32768
#define OFF_KHI 0
#define OFF_KLO 8192
#define OFF_VHI 16384
#define OFF_VLO 24576
#define SMEM_TOTAL (2 * STAGE_BYTES)   // 65536

__device__ __forceinline__ uint32_t smem_u32(const void* p) {
    uint32_t a;
    asm("{ .reg .u64 t; cvta.to.shared.u64 t, %1; cvt.u32.u64 %0, t; }" : "=r"(a) : "l"(p));
    return a;
}

// byte-offset swizzle for 128B rows: XOR row[2:0] into 16B-chunk index
__device__ __forceinline__ uint32_t swz(uint32_t b) { return b ^ ((b >> 3) & 0x70); }

__device__ __forceinline__ void mma_bf16(float* c, uint32_t a0, uint32_t a1,
                                         uint32_t a2, uint32_t a3,
                                         uint32_t b0, uint32_t b1) {
    asm volatile(
        "mma.sync.aligned.m16n8k16.row.col.f32.bf16.bf16.f32 "
        "{%0,%1,%2,%3}, {%4,%5,%6,%7}, {%8,%9}, {%0,%1,%2,%3};"
        : "+f"(c[0]), "+f"(c[1]), "+f"(c[2]), "+f"(c[3])
        : "r"(a0), "r"(a1), "r"(a2), "r"(a3), "r"(b0), "r"(b1));
}

__device__ __forceinline__ void ldsm4(uint32_t* r, uint32_t addr) {
    asm volatile("ldmatrix.sync.aligned.m8n8.x4.shared.b16 {%0,%1,%2,%3}, [%4];"
                 : "=r"(r[0]), "=r"(r[1]), "=r"(r[2]), "=r"(r[3]) : "r"(addr));
}
__device__ __forceinline__ void ldsm4t(uint32_t* r, uint32_t addr) {
    asm volatile("ldmatrix.sync.aligned.m8n8.x4.trans.shared.b16 {%0,%1,%2,%3}, [%4];"
                 : "=r"(r[0]), "=r"(r[1]), "=r"(r[2]), "=r"(r[3]) : "r"(addr));
}

__device__ __forceinline__ void cp_async16(uint32_t smem_dst, const void* gptr) {
    asm volatile("cp.async.cg.shared.global [%0], [%1], 16;"
                 :: "r"(smem_dst), "l"(gptr) : "memory");
}
#define CP_COMMIT() asm volatile("cp.async.commit_group;" ::: "memory")
#define CP_WAIT1()  asm volatile("cp.async.wait_group 1;" ::: "memory")
#define CP_WAIT0()  asm volatile("cp.async.wait_group 0;" ::: "memory")

// split (x,y) into packed bf16x2 hi and lo (residual) words
__device__ __forceinline__ void split2(float x, float y, uint32_t& hi, uint32_t& lo) {
    __nv_bfloat162 h = __floats2bfloat162_rn(x, y);
    float2 hf = __bfloat1622float2(h);
    __nv_bfloat162 l = __floats2bfloat162_rn(x - hf.x, y - hf.y);
    hi = *reinterpret_cast<uint32_t*>(&h);
    lo = *reinterpret_cast<uint32_t*>(&l);
}

// ---- prepass: split K and V into bf16 hi/lo scratch ----
__global__ __launch_bounds__(256)
void split_kv_kernel(const float* __restrict__ k, const float* __restrict__ v) {
    int idx = blockIdx.x * 256 + threadIdx.x;     // float4 index
    float4 kv = reinterpret_cast<const float4*>(k)[idx];
    uint32_t h0, l0, h1, l1;
    split2(kv.x, kv.y, h0, l0);
    split2(kv.z, kv.w, h1, l1);
    g_khi[idx] = make_uint2(h0, h1);
    g_klo[idx] = make_uint2(l0, l1);

    float4 vv = reinterpret_cast<const float4*>(v)[idx];
    split2(vv.x, vv.y, h0, l0);
    split2(vv.z, vv.w, h1, l1);
    g_vhi[idx] = make_uint2(h0, h1);
    g_vlo[idx] = make_uint2(l0, l1);
}

__global__ __launch_bounds__(256, 2)
void based_mma_kernel(const float* __restrict__ q, float* __restrict__ out)
{
    extern __shared__ char sm[];
    const uint32_t sbase = smem_u32(sm);

    const int tid  = threadIdx.x;
    const int lane = tid & 31;
    const int w    = tid >> 5;          // warp 0..7, owns q-rows [16w,16w+16)
    const int g    = lane >> 2;
    const int t4   = lane & 3;

    const int bh = blockIdx.y;
    const int qt = (NQT - 1) - blockIdx.x;   // big q-tiles first
    const size_t head = (size_t)bh * SEQ * DD;
    const int nkt = 2 * qt + 2;

    // bf16 tile byte base within scratch for this head (per-tile stride 8192B)
    const size_t headB = (size_t)bh * SEQ * DD * 2;   // bytes into g_* arrays
    const char* khiB = (const char*)g_khi + headB;
    const char* kloB = (const char*)g_klo + headB;
    const char* vhiB = (const char*)g_vhi + headB;
    const char* vloB = (const char*)g_vlo + headB;

    // issuer helper: thread copies 16B chunks tid, tid+256 of each of 4 tiles
    auto issue_tile = [&](int kt, int stage) {
        uint32_t sb = sbase + stage * STAGE_BYTES;
        size_t tb = (size_t)kt * 8192;    // tile byte offset (64*64*2)
        #pragma unroll
        for (int i = 0; i < 2; ++i) {
            int c = tid + i * 256;                    // chunk 0..511
            uint32_t so = swz((uint32_t)(c * 16));    // 16B-granular swizzle
            cp_async16(sb + OFF_KHI + so, khiB + tb + c * 16);
            cp_async16(sb + OFF_KLO + so, kloB + tb + c * 16);
            cp_async16(sb + OFF_VHI + so, vhiB + tb + c * 16);
            cp_async16(sb + OFF_VLO + so, vloB + tb + c * 16);
        }
        CP_COMMIT();
    };

    // ---- prologue: stage tile 0; then build Q fragments (hidden under copy) ----
    issue_tile(0, 0);

    uint32_t qh[4][4], ql[4][4];
    const int r0 = qt * QROWS + w * 16 + g;
    {
        const float scale = 0.125f;
        const float* qb = q + head;
        #pragma unroll
        for (int kb = 0; kb < 4; ++kb)
            #pragma unroll
            for (int h = 0; h < 4; ++h) {
                int row = r0 + ((h & 1) ? 8 : 0);
                int col = kb * 16 + t4 * 2 + ((h & 2) ? 8 : 0);
                float2 val = *reinterpret_cast<const float2*>(qb + (size_t)row * DD + col);
                split2(val.x * scale, val.y * scale, qh[kb][h], ql[kb][h]);
            }
    }

    float oacc[8][4] = {};

    const uint32_t sw = (lane & 7) << 4;
    const int rowK = ((lane >> 3) & 1) * 8 + (lane & 7);
    const int colK = (lane >> 4) * 16;
    const int rowV = ((lane >> 4) & 1) * 8 + (lane & 7);
    const int colV = ((lane >> 3) & 1) * 16;

    for (int kt = 0; kt < nkt; ++kt) {
        __syncthreads();    // all warps done reading the buffer we're about to refill
        if (kt + 1 < nkt) { issue_tile(kt + 1, (kt + 1) & 1); CP_WAIT1(); }
        else              { CP_WAIT0(); }
        __syncthreads();    // stage kt visible to all

        // warp fully masked on this k-tile? (only possible on last diagonal tile)
        if (kt * KROWS > qt * QROWS + w * 16 + 15) continue;

        const uint32_t sb = sbase + (kt & 1) * STAGE_BYTES;
        const uint32_t kh_b = sb + OFF_KHI, kl_b = sb + OFF_KLO;
        const uint32_t vh_b = sb + OFF_VHI, vl_b = sb + OFF_VLO;

        // ---- GEMM1: S[16x64] = Q_w * K^T  (3 split passes per B load) ----
        float sacc[8][4] = {};
        #pragma unroll
        for (int kk = 0; kk < 4; ++kk) {
            #pragma unroll
            for (int p = 0; p < 4; ++p) {
                uint32_t off = (uint32_t)((16 * p + rowK) * 128) + (((uint32_t)(32 * kk + colK)) ^ sw);
                uint32_t bhr[4], blr[4];
                ldsm4(bhr, kh_b + off);
                ldsm4(blr, kl_b + off);
                mma_bf16(sacc[2*p],   qh[kk][0],qh[kk][1],qh[kk][2],qh[kk][3], bhr[0], bhr[2]);
                mma_bf16(sacc[2*p+1], qh[kk][0],qh[kk][1],qh[kk][2],qh[kk][3], bhr[1], bhr[3]);
                mma_bf16(sacc[2*p],   qh[kk][0],qh[kk][1],qh[kk][2],qh[kk][3], blr[0], blr[2]);
                mma_bf16(sacc[2*p+1], qh[kk][0],qh[kk][1],qh[kk][2],qh[kk][3], blr[1], blr[3]);
                mma_bf16(sacc[2*p],   ql[kk][0],ql[kk][1],ql[kk][2],ql[kk][3], bhr[0], bhr[2]);
                mma_bf16(sacc[2*p+1], ql[kk][0],ql[kk][1],ql[kk][2],ql[kk][3], bhr[1], bhr[3]);
            }
        }

        // ---- phi(s)=s+0.5s^2, causal mask, split into GEMM2 A-fragments ----
        uint32_t ah[4][4], al[4][4];
        const bool edge = (kt >= 2 * qt);
        #pragma unroll
        for (int nb = 0; nb < 8; ++nb) {
            int colg = kt * KROWS + nb * 8 + 2 * t4;
            float e[4];
            #pragma unroll
            for (int u = 0; u < 4; ++u) {
                float s = sacc[nb][u];
                float p = fmaf(0.5f * s, s, s);
                if (edge && (colg + (u & 1) > r0 + ((u & 2) ? 8 : 0))) p = 0.0f;
                e[u] = p;
            }
            int kk = nb >> 1, half = (nb & 1) * 2;
            split2(e[0], e[1], ah[kk][half],     al[kk][half]);
            split2(e[2], e[3], ah[kk][half + 1], al[kk][half + 1]);
        }

        // ---- GEMM2: O += phi(S) * V  (V via ldmatrix.trans) ----
        #pragma unroll
        for (int kk = 0; kk < 4; ++kk) {
            #pragma unroll
            for (int p = 0; p < 4; ++p) {
                uint32_t off = (uint32_t)((16 * kk + rowV) * 128) + (((uint32_t)(32 * p + colV)) ^ sw);
                uint32_t vhr[4], vlr[4];
                ldsm4t(vhr, vh_b + off);
                ldsm4t(vlr, vl_b + off);
                mma_bf16(oacc[2*p],   ah[kk][0],ah[kk][1],ah[kk][2],ah[kk][3], vhr[0], vhr[2]);
                mma_bf16(oacc[2*p+1], ah[kk][0],ah[kk][1],ah[kk][2],ah[kk][3], vhr[1], vhr[3]);
                mma_bf16(oacc[2*p],   ah[kk][0],ah[kk][1],ah[kk][2],ah[kk][3], vlr[0], vlr[2]);
                mma_bf16(oacc[2*p+1], ah[kk][0],ah[kk][1],ah[kk][2],ah[kk][3], vlr[1], vlr[3]);
                mma_bf16(oacc[2*p],   al[kk][0],al[kk][1],al[kk][2],al[kk][3], vhr[0], vhr[2]);
                mma_bf16(oacc[2*p+1], al[kk][0],al[kk][1],al[kk][2],al[kk][3], vhr[1], vhr[3]);
            }
        }
    }

    // ---- store O fragments ----
    float* og = out + head;
    #pragma unroll
    for (int nb = 0; nb < 8; ++nb) {
        int col = nb * 8 + 2 * t4;
        *reinterpret_cast<float2*>(og + (size_t)r0 * DD + col) =
            make_float2(oacc[nb][0], oacc[nb][1]);
        *reinterpret_cast<float2*>(og + (size_t)(r0 + 8) * DD + col) =
            make_float2(oacc[nb][2], oacc[nb][3]);
    }
}

extern "C" void kernel_launch(void* const* d_in, const int* in_sizes, int n_in,
                              void* d_out, int out_size) {
    const float* q = (const float*)d_in[0];
    const float* k = (const float*)d_in[1];
    const float* v = (const float*)d_in[2];
    float* out = (float*)d_out;

    static bool attr_set = false;
    if (!attr_set) {
        cudaFuncSetAttribute(based_mma_kernel,
                             cudaFuncAttributeMaxDynamicSharedMemorySize, SMEM_TOTAL);
        attr_set = true;
    }

    split_kv_kernel<<<TOTAL_F4 / 256, 256>>>(k, v);
    dim3 grid(NQT, NBH);
    based_mma_kernel<<<grid, 256, SMEM_TOTAL>>>(q, out);
}